// round 15
// baseline (speedup 1.0000x reference)
#include <cuda_runtime.h>
#include <cuda_fp16.h>
#include <mma.h>
#include <math.h>
#include <stdint.h>

using namespace nvcuda;

// Problem constants (fixed shapes)
#define NB      128          // batch
#define SS      128          // seq
#define EE      1024         // embed
#define NQ      8            // qubits
#define NL      4            // layers
#define DIMQ    256          // 2^NQ
#define ROWS    16384        // NB*SS
#define KSPLIT  2048         // 2*EE  (fp16 2-term split: A=[hi|lo], B=[hi|hi])
#define KAV     256          // 2*SS  (attn@V split K)
#define Y_SIZE  16777216L    // NB*SS*EE

// Scratch (static device globals — allowed)
__device__ float  d_qin[ROWS * NQ];
__device__ float2 d_gates[NL * NQ * 4];
__device__ int    d_perm[DIMQ];
__device__ float2 d_psi[(long)ROWS * DIMQ];
__device__ float  d_V[(long)ROWS * EE];
__device__ __half d_Xs[(long)ROWS * KSPLIT];    // split X    [M][2K]
__device__ __half d_Ts[(long)ROWS * KSPLIT];    // split T    [M][2K]  (written by attn@V wgemm)
__device__ __half d_Wvs[(long)EE * KSPLIT];     // Wv^T       [N][2K] = [hi|hi]
__device__ __half d_Wos[(long)EE * KSPLIT];     // Wo^T       [N][2K] = [hi|hi]
__device__ __half d_attns[(long)ROWS * KAV];    // split attn [b*s][2*128] (written by gram)
__device__ __half d_Vts[(long)NB * EE * KAV];   // V^T        [b][e][2*128] = [hi|hi]

#define FULLM 0xffffffffu

// ---------------------------------------------------------------------------
// cp.async helpers (sm_80+ baseline — no 'a'-suffix features!)
// ---------------------------------------------------------------------------
__device__ __forceinline__ uint32_t smem_u32(const void* p) {
    uint32_t a;
    asm("{ .reg .u64 t; cvta.to.shared.u64 t, %1; cvt.u32.u64 %0, t; }" : "=r"(a) : "l"(p));
    return a;
}
__device__ __forceinline__ void cp16(uint32_t s, const void* g) {
    asm volatile("cp.async.cg.shared.global [%0], [%1], 16;" :: "r"(s), "l"(g));
}
#define CP_COMMIT() asm volatile("cp.async.commit_group;" ::: "memory")
#define CP_WAIT2()  asm volatile("cp.async.wait_group 2;" ::: "memory")
#define CP_WAIT1()  asm volatile("cp.async.wait_group 1;" ::: "memory")
#define CP_WAIT0()  asm volatile("cp.async.wait_group 0;" ::: "memory")

// ---------------------------------------------------------------------------
// Prep: fused RZ*RY gate matrices, composed CNOT-ring perm
// ---------------------------------------------------------------------------
__global__ void prep_kernel(const float* __restrict__ theta) {
    int t = threadIdx.x;
    if (t < NL * NQ) {
        float ty = theta[t * 2 + 0];
        float tz = theta[t * 2 + 1];
        float s, c, zs, zc;
        sincosf(0.5f * ty, &s, &c);
        sincosf(0.5f * tz, &zs, &zc);
        d_gates[t * 4 + 0] = make_float2( c * zc, -c * zs);
        d_gates[t * 4 + 1] = make_float2(-s * zc,  s * zs);
        d_gates[t * 4 + 2] = make_float2( s * zc,  s * zs);
        d_gates[t * 4 + 3] = make_float2( c * zc,  c * zs);
    }
    if (t < DIMQ) {
        int j = t;
        #pragma unroll
        for (int q = NQ - 1; q >= 0; q--) {
            int tq   = (q + 1) & (NQ - 1);
            int cpos = NQ - 1 - q;
            int tpos = NQ - 1 - tq;
            if ((j >> cpos) & 1) j ^= (1 << tpos);
        }
        d_perm[t] = j;
    }
}

// ---------------------------------------------------------------------------
// splitA: fp32 [R x 1024] -> fp16 [R x 2048] laid out [hi | lo]
// ---------------------------------------------------------------------------
__global__ __launch_bounds__(256) void splitA_kernel(const float* __restrict__ src,
                                                     __half* __restrict__ dst) {
    long i = (long)blockIdx.x * 256 + threadIdx.x;   // float4 index
    float4 v = ((const float4*)src)[i];
    long r  = i >> 8;
    int  c4 = (int)(i & 255) * 4;
    float vv[4] = {v.x, v.y, v.z, v.w};
    union { __half b[4]; uint2 u; } H, L;
    #pragma unroll
    for (int j = 0; j < 4; j++) {
        __half h = __float2half(vv[j]);
        H.b[j] = h;
        L.b[j] = __float2half(vv[j] - __half2float(h));
    }
    __half* row = dst + r * KSPLIT;
    *(uint2*)(row + c4)      = H.u;
    *(uint2*)(row + EE + c4) = L.u;
}

// ---------------------------------------------------------------------------
// splitB: W fp32 [K=1024][N=1024] -> Bt fp16 [N][2048] = [hi | hi] transposed
// ---------------------------------------------------------------------------
__global__ __launch_bounds__(256) void splitB_kernel(const float* __restrict__ W,
                                                     __half* __restrict__ Bt) {
    __shared__ float tile[32][33];
    int k0 = blockIdx.y * 32, n0 = blockIdx.x * 32;
    int tx = threadIdx.x & 31, ty = threadIdx.x >> 5;  // 32 x 8
    #pragma unroll
    for (int j = 0; j < 32; j += 8)
        tile[ty + j][tx] = W[(long)(k0 + ty + j) * EE + n0 + tx];
    __syncthreads();
    #pragma unroll
    for (int j = 0; j < 32; j += 8) {
        int n = n0 + ty + j, k = k0 + tx;
        __half h = __float2half(tile[tx][ty + j]);
        __half* row = Bt + (long)n * KSPLIT;
        row[k]      = h;
        row[EE + k] = h;
    }
}

// ---------------------------------------------------------------------------
// splitVt: V fp32 [b*128+t][e] -> Vts fp16 [b][e][256] = [hi(t) | hi(t)]
// ---------------------------------------------------------------------------
__global__ __launch_bounds__(256) void splitVt_kernel(const float* __restrict__ V,
                                                      __half* __restrict__ Vts) {
    __shared__ float tile[32][33];
    int b  = blockIdx.z;
    int t0 = blockIdx.y * 32, e0 = blockIdx.x * 32;
    int tx = threadIdx.x & 31, ty = threadIdx.x >> 5;  // 32 x 8
    #pragma unroll
    for (int j = 0; j < 32; j += 8)
        tile[ty + j][tx] = V[((long)b * SS + t0 + ty + j) * EE + e0 + tx];  // tile[t][e]
    __syncthreads();
    #pragma unroll
    for (int j = 0; j < 32; j += 8) {
        int e = e0 + ty + j, t = t0 + tx;
        __half h = __float2half(tile[tx][ty + j]);
        __half* row = Vts + ((long)b * EE + e) * KAV;
        row[t]      = h;
        row[SS + t] = h;
    }
}

// ---------------------------------------------------------------------------
// wmma (HMMA) fp16 GEMM: C = A'[M,LDA] x B'[1024,LDA]^T, z-batched.
// BM=BN=128, BK=32, 256 threads (8 warps, 4x2), warp tile 32x64 (2x4 frags),
// THREE-stage cp.async pipeline (60KB dynamic smem).
// MODE 0: fp32 C (stride EE) + bias.   MODE 1: fp16 [hi|lo] out (stride KSPLIT).
// ---------------------------------------------------------------------------
#define WG_LDS    40                  // smem row stride (fp16 elems), 80 bytes
#define WG_HALF   (128 * WG_LDS)      // 5120 elems = 10240 bytes per matrix
#define WG_STAGE  (2 * WG_HALF * 2)   // A+B per stage = 20480 bytes
#define WG_NSTG   3
#define WG_SMEM   (WG_NSTG * WG_STAGE)  // 61440 bytes

template<int LDA, int NCH, int MODE>
__global__ __launch_bounds__(256) void wgemm_kernel(
    const __half* __restrict__ A, const __half* __restrict__ B,
    const float* __restrict__ bias, float* __restrict__ C,
    __half* __restrict__ aux, long sA, long sB, long sC) {
    extern __shared__ __align__(16) char smem_raw[];
    uint32_t sbase = smem_u32(smem_raw);

    int tid  = threadIdx.x;
    int wid  = tid >> 5, lane = tid & 31;
    int wm   = wid & 3;         // warp row: rows [wm*32, wm*32+32)
    int wn   = wid >> 2;        // warp col: cols [wn*64, wn*64+64)

    long bz = blockIdx.z;
    const __half* Ab = A + bz * sA;
    const __half* Bb = B + bz * sB;

    long m0 = (long)blockIdx.y * 128;
    int  n0 = blockIdx.x * 128;

    // cp.async mapping: tile 128x32 fp16 = 512 x 16B segs; 2 per thread per matrix.
    uint32_t dstO[2];
    const char* srcA[2];
    const char* srcB[2];
    #pragma unroll
    for (int u = 0; u < 2; u++) {
        int idx = tid + 256 * u;
        int row = idx >> 2, seg = idx & 3;
        dstO[u] = (uint32_t)row * (WG_LDS * 2) + seg * 16;
        srcA[u] = (const char*)(Ab + (m0 + row) * (long)LDA) + seg * 16;
        srcB[u] = (const char*)(Bb + (long)(n0 + row) * LDA) + seg * 16;
    }

    wmma::fragment<wmma::accumulator, 16, 16, 16, float> acc[2][4];
    #pragma unroll
    for (int i = 0; i < 2; i++)
        #pragma unroll
        for (int j = 0; j < 4; j++) wmma::fill_fragment(acc[i][j], 0.f);

    // prologue: chunks 0,1 -> stages 0,1   (B at byte offset 2*WG_HALF = 10240)
    #pragma unroll
    for (int p = 0; p < 2; p++) {
        uint32_t st = sbase + p * WG_STAGE;
        long gofs = (long)p * 64;
        #pragma unroll
        for (int u = 0; u < 2; u++) {
            cp16(st + dstO[u], srcA[u] + gofs);
            cp16(st + 2 * WG_HALF + dstO[u], srcB[u] + gofs);
        }
        CP_COMMIT();
    }

    int stage = 0;      // stage holding chunk ch
    int nstage = 2;     // stage to fill with chunk ch+2
    #pragma unroll 1
    for (int ch = 0; ch < NCH; ch++) {
        if (ch + 2 < NCH) {
            uint32_t st = sbase + nstage * WG_STAGE;
            long gofs = (long)(ch + 2) * 64;
            #pragma unroll
            for (int u = 0; u < 2; u++) {
                cp16(st + dstO[u], srcA[u] + gofs);
                cp16(st + 2 * WG_HALF + dstO[u], srcB[u] + gofs);
            }
            CP_COMMIT();
            CP_WAIT2();
        } else if (ch + 1 < NCH) {
            CP_WAIT1();
        } else {
            CP_WAIT0();
        }
        __syncthreads();

        const __half* bufA = (const __half*)(smem_raw + stage * WG_STAGE);
        const __half* bufB = bufA + WG_HALF;   // +5120 elems = +10240 BYTES (matches store)

        #pragma unroll
        for (int kk = 0; kk < 32; kk += 16) {
            wmma::fragment<wmma::matrix_a, 16, 16, 16, __half, wmma::row_major> af[2];
            wmma::fragment<wmma::matrix_b, 16, 16, 16, __half, wmma::col_major> bf[4];
            #pragma unroll
            for (int i = 0; i < 2; i++)
                wmma::load_matrix_sync(af[i], bufA + (wm * 32 + i * 16) * WG_LDS + kk, WG_LDS);
            #pragma unroll
            for (int j = 0; j < 4; j++)
                wmma::load_matrix_sync(bf[j], bufB + (wn * 64 + j * 16) * WG_LDS + kk, WG_LDS);
            #pragma unroll
            for (int i = 0; i < 2; i++)
                #pragma unroll
                for (int j = 0; j < 4; j++)
                    wmma::mma_sync(acc[i][j], af[i], bf[j], acc[i][j]);
        }
        __syncthreads();
        stage  = (stage == WG_NSTG - 1) ? 0 : stage + 1;
        nstage = (nstage == WG_NSTG - 1) ? 0 : nstage + 1;
    }

    // Epilogue: per-warp SMEM staging (16x68 f32) -> coalesced stores
    float* stag = (float*)smem_raw + wid * (16 * 68);   // 8 warps x 4352B = 34816
    int erow = lane >> 1, ecb = (lane & 1) * 32;
    float* Cb = (MODE == 0) ? (C + bz * sC) : nullptr;
    __half* Ab2 = (MODE == 1) ? (aux + bz * sC) : nullptr;
    #pragma unroll
    for (int mi = 0; mi < 2; mi++) {
        #pragma unroll
        for (int j = 0; j < 4; j++)
            wmma::store_matrix_sync(stag + j * 16, acc[mi][j], 68, wmma::mem_row_major);
        __syncwarp();
        long grow = m0 + wm * 32 + mi * 16 + erow;
        int  gcol = n0 + wn * 64 + ecb;
        #pragma unroll
        for (int f = 0; f < 8; f++) {
            float4 v = *(float4*)(stag + erow * 68 + ecb + f * 4);
            if (MODE == 0) {
                if (bias) {
                    float4 b4 = *(const float4*)(bias + gcol + f * 4);
                    v.x += b4.x; v.y += b4.y; v.z += b4.z; v.w += b4.w;
                }
                *(float4*)(Cb + grow * EE + gcol + f * 4) = v;
            } else {
                float vv[4] = {v.x, v.y, v.z, v.w};
                union { __half b[4]; uint2 u; } H, L;
                #pragma unroll
                for (int q = 0; q < 4; q++) {
                    __half h = __float2half(vv[q]);
                    H.b[q] = h;
                    L.b[q] = __float2half(vv[q] - __half2float(h));
                }
                __half* rowp = Ab2 + grow * KSPLIT + gcol + f * 4;
                *(uint2*)(rowp)      = H.u;
                *(uint2*)(rowp + EE) = L.u;
            }
        }
        __syncwarp();
    }
}

// ---------------------------------------------------------------------------
// qin = X @ Wi + bi    (16384x8, K=1024) : one warp per row
// ---------------------------------------------------------------------------
__global__ __launch_bounds__(256) void qin_kernel(const float* __restrict__ X,
                                                  const float* __restrict__ Wi,
                                                  const float* __restrict__ bi) {
    __shared__ float sWi[NQ * EE];
    int tid = threadIdx.x;
    for (int idx = tid; idx < EE * NQ; idx += 256) {
        int k = idx >> 3, o = idx & 7;
        sWi[o * EE + k] = Wi[idx];
    }
    __syncthreads();

    int w = tid >> 5, lane = tid & 31;
    long row = (long)blockIdx.x * 8 + w;
    const float* xr = X + row * EE;

    float acc[NQ];
    #pragma unroll
    for (int o = 0; o < NQ; o++) acc[o] = 0.f;
    for (int k = lane; k < EE; k += 32) {
        float x = xr[k];
        #pragma unroll
        for (int o = 0; o < NQ; o++) acc[o] += x * sWi[o * EE + k];
    }
    float out = 0.f;
    #pragma unroll
    for (int o = 0; o < NQ; o++) {
        float v = acc[o];
        #pragma unroll
        for (int d = 16; d > 0; d >>= 1) v += __shfl_xor_sync(FULLM, v, d);
        if (lane == o) out = v + bi[o];
    }
    if (lane < NQ) d_qin[row * NQ + lane] = out;
}

// ---------------------------------------------------------------------------
// Quantum state sim — REGISTER-RESIDENT state.
// One warp per row; lane L owns 8 consecutive amplitudes i = 8L + o.
// Bit b of i (b = 7-q): b<3 -> thread-local pair; b>=3 -> shfl_xor(lane bit b-3).
// Composed CNOT permutation via one smem round-trip per layer.
// ---------------------------------------------------------------------------
__global__ __launch_bounds__(256) void psi_kernel() {
    __shared__ float2 st[8][DIMQ];       // 16KB perm staging
    __shared__ float2 gm[NL * NQ * 4];
    __shared__ int    pm[DIMQ];

    int tid = threadIdx.x;
    if (tid < NL * NQ * 4) gm[tid] = d_gates[tid];
    pm[tid] = d_perm[tid];
    __syncthreads();

    int w = tid >> 5, lane = tid & 31;
    long row = (long)blockIdx.x * 8 + w;

    // initial product state
    float x = (lane < NQ) ? d_qin[row * NQ + lane] : 0.f;
    float ss, cc;
    sincosf(0.5f * x, &ss, &cc);
    float cq[NQ], sq[NQ];
    #pragma unroll
    for (int q = 0; q < NQ; q++) {
        cq[q] = __shfl_sync(FULLM, cc, q);
        sq[q] = __shfl_sync(FULLM, ss, q);
    }
    float ar[8], ai[8];
    #pragma unroll
    for (int o = 0; o < 8; o++) {
        int i = 8 * lane + o;
        float a = 1.f;
        #pragma unroll
        for (int q = 0; q < NQ; q++)
            a *= ((i >> (NQ - 1 - q)) & 1) ? sq[q] : cq[q];
        ar[o] = a; ai[o] = 0.f;
    }

    #pragma unroll 1
    for (int l = 0; l < NL; l++) {
        #pragma unroll
        for (int q = 0; q < NQ; q++) {
            const float2 m00 = gm[(l * NQ + q) * 4 + 0];
            const float2 m01 = gm[(l * NQ + q) * 4 + 1];
            const float2 m10 = gm[(l * NQ + q) * 4 + 2];
            const float2 m11 = gm[(l * NQ + q) * 4 + 3];
            const int b = NQ - 1 - q;      // bit index of i
            if (b < 3) {
                // thread-local pairs: (o, o | (1<<b))
                const int s = 1 << b;
                #pragma unroll
                for (int o0 = 0; o0 < 8; o0++) {
                    if (o0 & s) continue;
                    int o1 = o0 | s;
                    float a0r = ar[o0], a0i = ai[o0];
                    float a1r = ar[o1], a1i = ai[o1];
                    ar[o0] = m00.x * a0r - m00.y * a0i + m01.x * a1r - m01.y * a1i;
                    ai[o0] = m00.x * a0i + m00.y * a0r + m01.x * a1i + m01.y * a1r;
                    ar[o1] = m10.x * a0r - m10.y * a0i + m11.x * a1r - m11.y * a1i;
                    ai[o1] = m10.x * a0i + m10.y * a0r + m11.x * a1i + m11.y * a1r;
                }
            } else {
                // lane-exchange pairs: partner lane = lane ^ (1 << (b-3))
                const int msk = 1 << (b - 3);
                const bool up = (lane >> (b - 3)) & 1;   // I hold the |1> half
                const float2 cA = up ? m10 : m00;         // applies to lower value
                const float2 cB = up ? m11 : m01;         // applies to upper value
                #pragma unroll
                for (int o = 0; o < 8; o++) {
                    float pr = __shfl_xor_sync(FULLM, ar[o], msk);
                    float pi = __shfl_xor_sync(FULLM, ai[o], msk);
                    float a0r = up ? pr : ar[o], a0i = up ? pi : ai[o];
                    float a1r = up ? ar[o] : pr, a1i = up ? ai[o] : pi;
                    ar[o] = cA.x * a0r - cA.y * a0i + cB.x * a1r - cB.y * a1i;
                    ai[o] = cA.x * a0i + cA.y * a0r + cB.x * a1i + cB.y * a1r;
                }
            }
        }
        // composed CNOT-ring permutation (smem gather)
        #pragma unroll
        for (int o = 0; o < 8; o++) st[w][8 * lane + o] = make_float2(ar[o], ai[o]);
        __syncwarp();
        #pragma unroll
        for (int o = 0; o < 8; o++) {
            float2 v = st[w][pm[8 * lane + o]];
            ar[o] = v.x; ai[o] = v.y;
        }
        __syncwarp();
    }

    // store: lane L writes 64B contiguous
    float2* out = d_psi + row * DIMQ + 8 * lane;
    #pragma unroll
    for (int o = 0; o < 8; o++) out[o] = make_float2(ar[o], ai[o]);
}

// ---------------------------------------------------------------------------
// Gram + kernel-matrix + softmax -> attn (fp32) + fused fp16 [hi|lo] split.
// TWO blocks per batch (64 s-rows each), 512 threads.
// ---------------------------------------------------------------------------
__global__ __launch_bounds__(512) void gram_kernel(const float* __restrict__ phi,
                                                   float* __restrict__ attn,
                                                   __half* __restrict__ attns) {
    const int DC = 16;
    __shared__ float2 P[SS][DC + 1];

    int b   = blockIdx.x;
    int sh  = blockIdx.y;      // 0/1 -> s-rows [sh*64, sh*64+64)
    int tid = threadIdx.x;
    int ts  = tid >> 5;
    int tt  = tid & 31;

    float accr[4][4], acci[4][4];
    #pragma unroll
    for (int j = 0; j < 4; j++)
        #pragma unroll
        for (int k = 0; k < 4; k++) { accr[j][k] = 0.f; acci[j][k] = 0.f; }

    const float2* pb = d_psi + (long)b * SS * DIMQ;

    for (int d0 = 0; d0 < DIMQ; d0 += DC) {
        #pragma unroll
        for (int u = 0; u < 4; u++) {
            int idx = tid + 512 * u;
            int r = idx >> 4, dd = idx & 15;
            P[r][dd] = pb[(long)r * DIMQ + d0 + dd];
        }
        __syncthreads();
        #pragma unroll 4
        for (int dd = 0; dd < DC; dd++) {
            float2 sf[4], tf[4];
            #pragma unroll
            for (int j = 0; j < 4; j++) sf[j] = P[sh * 64 + ts * 4 + j][dd];
            #pragma unroll
            for (int k = 0; k < 4; k++) tf[k] = P[tt + 32 * k][dd];
            #pragma unroll
            for (int j = 0; j < 4; j++)
                #pragma unroll
                for (int k = 0; k < 4; k++) {
                    accr[j][k] += sf[j].x * tf[k].x + sf[j].y * tf[k].y;
                    acci[j][k] += sf[j].y * tf[k].x - sf[j].x * tf[k].y;
                }
        }
        __syncthreads();
    }

    const float inv = 0.3535533905932738f;
    float pht[4];
    #pragma unroll
    for (int k = 0; k < 4; k++) pht[k] = phi[tt + 32 * k];

    #pragma unroll
    for (int j = 0; j < 4; j++) {
        int srow = sh * 64 + ts * 4 + j;
        float ph_s = phi[srow];
        float kv[4];
        float mx = -1e30f;
        #pragma unroll
        for (int k = 0; k < 4; k++) {
            float g2 = accr[j][k] * accr[j][k] + acci[j][k] * acci[j][k];
            kv[k] = g2 * inv + cosf(pht[k] - ph_s);
            mx = fmaxf(mx, kv[k]);
        }
        #pragma unroll
        for (int d = 16; d > 0; d >>= 1) mx = fmaxf(mx, __shfl_xor_sync(FULLM, mx, d));
        float sum = 0.f;
        #pragma unroll
        for (int k = 0; k < 4; k++) { kv[k] = expf(kv[k] - mx); sum += kv[k]; }
        #pragma unroll
        for (int d = 16; d > 0; d >>= 1) sum += __shfl_xor_sync(FULLM, sum, d);
        float is = 1.f / sum;
        long arow = (long)b * SS + srow;
        #pragma unroll
        for (int k = 0; k < 4; k++) {
            float a = kv[k] * is;
            attn[(long)b * SS * SS + (long)srow * SS + tt + 32 * k] = a;
            __half h = __float2half(a);
            __half l = __float2half(a - __half2float(h));
            attns[arow * KAV + tt + 32 * k]      = h;
            attns[arow * KAV + SS + tt + 32 * k] = l;
        }
    }
}

// ---------------------------------------------------------------------------
extern "C" void kernel_launch(void* const* d_in, const int* in_sizes, int n_in,
                              void* d_out, int out_size) {
    const float* X     = (const float*)d_in[0];
    const float* Wi    = (const float*)d_in[1];
    const float* bi    = (const float*)d_in[2];
    const float* Wv    = (const float*)d_in[3];
    const float* bv    = (const float*)d_in[4];
    const float* Wo    = (const float*)d_in[5];
    const float* bo    = (const float*)d_in[6];
    const float* theta = (const float*)d_in[7];
    const float* phi   = (const float*)d_in[8];

    float* y    = (float*)d_out;
    float* attn = (float*)d_out + Y_SIZE;

    float *pV;
    __half *pXs, *pTs, *pWvs, *pWos, *pAs, *pVts;
    cudaGetSymbolAddress((void**)&pV, d_V);
    cudaGetSymbolAddress((void**)&pXs, d_Xs);
    cudaGetSymbolAddress((void**)&pTs, d_Ts);
    cudaGetSymbolAddress((void**)&pWvs, d_Wvs);
    cudaGetSymbolAddress((void**)&pWos, d_Wos);
    cudaGetSymbolAddress((void**)&pAs, d_attns);
    cudaGetSymbolAddress((void**)&pVts, d_Vts);

    // dynamic smem opt-in (host-side attribute config; idempotent)
    cudaFuncSetAttribute((const void*)wgemm_kernel<KSPLIT, KSPLIT / 32, 0>,
                         cudaFuncAttributeMaxDynamicSharedMemorySize, WG_SMEM);
    cudaFuncSetAttribute((const void*)wgemm_kernel<KAV, KAV / 32, 1>,
                         cudaFuncAttributeMaxDynamicSharedMemorySize, WG_SMEM);

    // prep + splits
    prep_kernel<<<1, 256>>>(theta);
    {
        dim3 g(EE / 32, EE / 32);
        splitB_kernel<<<g, 256>>>(Wv, pWvs);
        splitB_kernel<<<g, 256>>>(Wo, pWos);
    }
    splitA_kernel<<<ROWS, 256>>>(X, pXs);
    qin_kernel<<<ROWS / 8, 256>>>(X, Wi, bi);

    // V = X@Wv + bv  (wmma fp16 2-term, 3-stage pipeline)
    {
        dim3 grid(EE / 128, ROWS / 128, 1);
        wgemm_kernel<KSPLIT, KSPLIT / 32, 0><<<grid, 256, WG_SMEM>>>(
            pXs, pWvs, bv, pV, nullptr, 0, 0, 0);
    }

    // quantum states + Gram/softmax (writes fp32 attn + fp16 split)
    psi_kernel<<<ROWS / 8, 256>>>();
    gram_kernel<<<dim3(NB, 2), 512>>>(phi, attn, pAs);

    // V^T split for attn@V
    {
        dim3 g(EE / 32, SS / 32, NB);
        splitVt_kernel<<<g, 256>>>(pV, pVts);
    }

    // T = attn @ V (wmma, batched over z) -> emits Ts = [hi|lo] fp16 directly
    {
        dim3 grid(EE / 128, 1, NB);
        wgemm_kernel<KAV, KAV / 32, 1><<<grid, 256, WG_SMEM>>>(
            pAs, pVts, nullptr, nullptr, pTs,
            (long)SS * KAV, (long)EE * KAV, (long)SS * KSPLIT);
    }

    // y = T @ Wo + bo (wmma fp16 2-term, 3-stage pipeline)
    {
        dim3 grid(EE / 128, ROWS / 128, 1);
        wgemm_kernel<KSPLIT, KSPLIT / 32, 0><<<grid, 256, WG_SMEM>>>(
            pTs, pWos, bo, y, nullptr, 0, 0, 0);
    }
}

// round 16
// speedup vs baseline: 1.5598x; 1.5598x over previous
#include <cuda_runtime.h>
#include <cuda_fp16.h>
#include <mma.h>
#include <math.h>
#include <stdint.h>

using namespace nvcuda;

// Problem constants (fixed shapes)
#define NB      128          // batch
#define SS      128          // seq
#define EE      1024         // embed
#define NQ      8            // qubits
#define NL      4            // layers
#define DIMQ    256          // 2^NQ
#define ROWS    16384        // NB*SS
#define KSPLIT  2048         // 2*EE  (fp16 2-term split: A=[hi|lo], B=[hi|hi])
#define KAV     256          // 2*SS  (attn@V split K)
#define Y_SIZE  16777216L    // NB*SS*EE

// Scratch (static device globals — allowed)
__device__ float  d_qin[ROWS * NQ];
__device__ float2 d_gates[NL * NQ * 4];
__device__ int    d_perm[DIMQ];
__device__ float2 d_psi[(long)ROWS * DIMQ];
__device__ __half d_Xs[(long)ROWS * KSPLIT];    // split X    [M][2K]
__device__ __half d_Ts[(long)ROWS * KSPLIT];    // split T    [M][2K]  (written by attn@V wgemm)
__device__ __half d_Wvs[(long)EE * KSPLIT];     // Wv^T       [N][2K] = [hi|hi]
__device__ __half d_Wos[(long)EE * KSPLIT];     // Wo^T       [N][2K] = [hi|hi]
__device__ __half d_attns[(long)ROWS * KAV];    // split attn [b*s][2*128] (written by gram)
__device__ __half d_Vts[(long)NB * EE * KAV];   // V^T        [b][e][2*128] = [hi|hi] (written by V wgemm)

#define FULLM 0xffffffffu

// ---------------------------------------------------------------------------
// cp.async helpers (sm_80+ baseline — no 'a'-suffix features!)
// ---------------------------------------------------------------------------
__device__ __forceinline__ uint32_t smem_u32(const void* p) {
    uint32_t a;
    asm("{ .reg .u64 t; cvta.to.shared.u64 t, %1; cvt.u32.u64 %0, t; }" : "=r"(a) : "l"(p));
    return a;
}
__device__ __forceinline__ void cp16(uint32_t s, const void* g) {
    asm volatile("cp.async.cg.shared.global [%0], [%1], 16;" :: "r"(s), "l"(g));
}
#define CP_COMMIT() asm volatile("cp.async.commit_group;" ::: "memory")
#define CP_WAIT2()  asm volatile("cp.async.wait_group 2;" ::: "memory")
#define CP_WAIT1()  asm volatile("cp.async.wait_group 1;" ::: "memory")
#define CP_WAIT0()  asm volatile("cp.async.wait_group 0;" ::: "memory")

// ---------------------------------------------------------------------------
// Prep: fused RZ*RY gate matrices, composed CNOT-ring perm
// ---------------------------------------------------------------------------
__global__ void prep_kernel(const float* __restrict__ theta) {
    int t = threadIdx.x;
    if (t < NL * NQ) {
        float ty = theta[t * 2 + 0];
        float tz = theta[t * 2 + 1];
        float s, c, zs, zc;
        sincosf(0.5f * ty, &s, &c);
        sincosf(0.5f * tz, &zs, &zc);
        d_gates[t * 4 + 0] = make_float2( c * zc, -c * zs);
        d_gates[t * 4 + 1] = make_float2(-s * zc,  s * zs);
        d_gates[t * 4 + 2] = make_float2( s * zc,  s * zs);
        d_gates[t * 4 + 3] = make_float2( c * zc,  c * zs);
    }
    if (t < DIMQ) {
        int j = t;
        #pragma unroll
        for (int q = NQ - 1; q >= 0; q--) {
            int tq   = (q + 1) & (NQ - 1);
            int cpos = NQ - 1 - q;
            int tpos = NQ - 1 - tq;
            if ((j >> cpos) & 1) j ^= (1 << tpos);
        }
        d_perm[t] = j;
    }
}

// ---------------------------------------------------------------------------
// splitA: fp32 [R x 1024] -> fp16 [R x 2048] laid out [hi | lo]
// ---------------------------------------------------------------------------
__global__ __launch_bounds__(256) void splitA_kernel(const float* __restrict__ src,
                                                     __half* __restrict__ dst) {
    long i = (long)blockIdx.x * 256 + threadIdx.x;   // float4 index
    float4 v = ((const float4*)src)[i];
    long r  = i >> 8;
    int  c4 = (int)(i & 255) * 4;
    float vv[4] = {v.x, v.y, v.z, v.w};
    union { __half b[4]; uint2 u; } H, L;
    #pragma unroll
    for (int j = 0; j < 4; j++) {
        __half h = __float2half(vv[j]);
        H.b[j] = h;
        L.b[j] = __float2half(vv[j] - __half2float(h));
    }
    __half* row = dst + r * KSPLIT;
    *(uint2*)(row + c4)      = H.u;
    *(uint2*)(row + EE + c4) = L.u;
}

// ---------------------------------------------------------------------------
// splitB: W fp32 [K=1024][N=1024] -> Bt fp16 [N][2048] = [hi | hi] transposed
// ---------------------------------------------------------------------------
__global__ __launch_bounds__(256) void splitB_kernel(const float* __restrict__ W,
                                                     __half* __restrict__ Bt) {
    __shared__ float tile[32][33];
    int k0 = blockIdx.y * 32, n0 = blockIdx.x * 32;
    int tx = threadIdx.x & 31, ty = threadIdx.x >> 5;  // 32 x 8
    #pragma unroll
    for (int j = 0; j < 32; j += 8)
        tile[ty + j][tx] = W[(long)(k0 + ty + j) * EE + n0 + tx];
    __syncthreads();
    #pragma unroll
    for (int j = 0; j < 32; j += 8) {
        int n = n0 + ty + j, k = k0 + tx;
        __half h = __float2half(tile[tx][ty + j]);
        __half* row = Bt + (long)n * KSPLIT;
        row[k]      = h;
        row[EE + k] = h;
    }
}

// ---------------------------------------------------------------------------
// wmma (HMMA) fp16 GEMM: C = A'[M,LDA] x B'[1024,LDA]^T, z-batched.
// BM=BN=128, BK=32, 256 threads (8 warps, 4x2), warp tile 32x64 (2x4 frags),
// THREE-stage cp.async pipeline (60KB dynamic smem).
// MODE 0: fp32 C (stride EE) + bias.
// MODE 1: fp16 [hi|lo] out (row stride KSPLIT).
// MODE 2: fp16 [hi|hi] TRANSPOSED out into Vts[b][e][KAV] + bias (V GEMM).
// ---------------------------------------------------------------------------
#define WG_LDS    40                  // smem row stride (fp16 elems), 80 bytes
#define WG_HALF   (128 * WG_LDS)      // 5120 elems = 10240 bytes per matrix
#define WG_STAGE  (2 * WG_HALF * 2)   // A+B per stage = 20480 bytes
#define WG_NSTG   3
#define WG_SMEM   (WG_NSTG * WG_STAGE)  // 61440 bytes

template<int LDA, int NCH, int MODE>
__global__ __launch_bounds__(256) void wgemm_kernel(
    const __half* __restrict__ A, const __half* __restrict__ B,
    const float* __restrict__ bias, float* __restrict__ C,
    __half* __restrict__ aux, long sA, long sB, long sC) {
    extern __shared__ __align__(16) char smem_raw[];
    uint32_t sbase = smem_u32(smem_raw);

    int tid  = threadIdx.x;
    int wid  = tid >> 5, lane = tid & 31;
    int wm   = wid & 3;         // warp row: rows [wm*32, wm*32+32)
    int wn   = wid >> 2;        // warp col: cols [wn*64, wn*64+64)

    long bz = blockIdx.z;
    const __half* Ab = A + bz * sA;
    const __half* Bb = B + bz * sB;

    long m0 = (long)blockIdx.y * 128;
    int  n0 = blockIdx.x * 128;

    // cp.async mapping: tile 128x32 fp16 = 512 x 16B segs; 2 per thread per matrix.
    uint32_t dstO[2];
    const char* srcA[2];
    const char* srcB[2];
    #pragma unroll
    for (int u = 0; u < 2; u++) {
        int idx = tid + 256 * u;
        int row = idx >> 2, seg = idx & 3;
        dstO[u] = (uint32_t)row * (WG_LDS * 2) + seg * 16;
        srcA[u] = (const char*)(Ab + (m0 + row) * (long)LDA) + seg * 16;
        srcB[u] = (const char*)(Bb + (long)(n0 + row) * LDA) + seg * 16;
    }

    wmma::fragment<wmma::accumulator, 16, 16, 16, float> acc[2][4];
    #pragma unroll
    for (int i = 0; i < 2; i++)
        #pragma unroll
        for (int j = 0; j < 4; j++) wmma::fill_fragment(acc[i][j], 0.f);

    // prologue: chunks 0,1 -> stages 0,1   (B at byte offset 2*WG_HALF = 10240)
    #pragma unroll
    for (int p = 0; p < 2; p++) {
        uint32_t st = sbase + p * WG_STAGE;
        long gofs = (long)p * 64;
        #pragma unroll
        for (int u = 0; u < 2; u++) {
            cp16(st + dstO[u], srcA[u] + gofs);
            cp16(st + 2 * WG_HALF + dstO[u], srcB[u] + gofs);
        }
        CP_COMMIT();
    }

    int stage = 0;      // stage holding chunk ch
    int nstage = 2;     // stage to fill with chunk ch+2
    #pragma unroll 1
    for (int ch = 0; ch < NCH; ch++) {
        if (ch + 2 < NCH) {
            uint32_t st = sbase + nstage * WG_STAGE;
            long gofs = (long)(ch + 2) * 64;
            #pragma unroll
            for (int u = 0; u < 2; u++) {
                cp16(st + dstO[u], srcA[u] + gofs);
                cp16(st + 2 * WG_HALF + dstO[u], srcB[u] + gofs);
            }
            CP_COMMIT();
            CP_WAIT2();
        } else if (ch + 1 < NCH) {
            CP_WAIT1();
        } else {
            CP_WAIT0();
        }
        __syncthreads();

        const __half* bufA = (const __half*)(smem_raw + stage * WG_STAGE);
        const __half* bufB = bufA + WG_HALF;   // +5120 elems = +10240 BYTES (matches store)

        #pragma unroll
        for (int kk = 0; kk < 32; kk += 16) {
            wmma::fragment<wmma::matrix_a, 16, 16, 16, __half, wmma::row_major> af[2];
            wmma::fragment<wmma::matrix_b, 16, 16, 16, __half, wmma::col_major> bf[4];
            #pragma unroll
            for (int i = 0; i < 2; i++)
                wmma::load_matrix_sync(af[i], bufA + (wm * 32 + i * 16) * WG_LDS + kk, WG_LDS);
            #pragma unroll
            for (int j = 0; j < 4; j++)
                wmma::load_matrix_sync(bf[j], bufB + (wn * 64 + j * 16) * WG_LDS + kk, WG_LDS);
            #pragma unroll
            for (int i = 0; i < 2; i++)
                #pragma unroll
                for (int j = 0; j < 4; j++)
                    wmma::mma_sync(acc[i][j], af[i], bf[j], acc[i][j]);
        }
        __syncthreads();
        stage  = (stage == WG_NSTG - 1) ? 0 : stage + 1;
        nstage = (nstage == WG_NSTG - 1) ? 0 : nstage + 1;
    }

    // Epilogue: per-warp SMEM staging (16x68 f32) -> stores by MODE
    float* stag = (float*)smem_raw + wid * (16 * 68);   // 8 warps x 4352B = 34816
    int erow = lane >> 1, ecb = (lane & 1) * 32;
    float* Cb = (MODE == 0) ? (C + bz * sC) : nullptr;
    __half* Ab2 = (MODE == 1) ? (aux + bz * sC) : nullptr;
    #pragma unroll
    for (int mi = 0; mi < 2; mi++) {
        #pragma unroll
        for (int j = 0; j < 4; j++)
            wmma::store_matrix_sync(stag + j * 16, acc[mi][j], 68, wmma::mem_row_major);
        __syncwarp();
        if (MODE == 2) {
            // Transposed fp16 [hi|hi] output with bias: Vts[(b*EE + e)*KAV + t].
            // Tile rows = t (16 of them, base tb), cols = e (64). m0 is 128-aligned
            // so the whole tile is one batch b = blockIdx.y.
            int b  = blockIdx.y;
            int tb = wm * 32 + mi * 16;
            #pragma unroll
            for (int cc = 0; cc < 2; cc++) {
                int ecol = lane * 2 + cc;             // 0..63
                int eg   = n0 + wn * 64 + ecol;
                float be = bias[eg];
                union { __half h[16]; uint4 u[2]; } pk;
                #pragma unroll
                for (int r = 0; r < 16; r++)
                    pk.h[r] = __float2half(stag[r * 68 + ecol] + be);
                __half* rowp = aux + ((long)b * EE + eg) * KAV + tb;
                *(uint4*)(rowp)          = pk.u[0];
                *(uint4*)(rowp + 8)      = pk.u[1];
                *(uint4*)(rowp + SS)     = pk.u[0];
                *(uint4*)(rowp + SS + 8) = pk.u[1];
            }
        } else {
            long grow = m0 + wm * 32 + mi * 16 + erow;
            int  gcol = n0 + wn * 64 + ecb;
            #pragma unroll
            for (int f = 0; f < 8; f++) {
                float4 v = *(float4*)(stag + erow * 68 + ecb + f * 4);
                if (MODE == 0) {
                    if (bias) {
                        float4 b4 = *(const float4*)(bias + gcol + f * 4);
                        v.x += b4.x; v.y += b4.y; v.z += b4.z; v.w += b4.w;
                    }
                    *(float4*)(Cb + grow * EE + gcol + f * 4) = v;
                } else {
                    float vv[4] = {v.x, v.y, v.z, v.w};
                    union { __half b[4]; uint2 u; } H, L;
                    #pragma unroll
                    for (int q = 0; q < 4; q++) {
                        __half h = __float2half(vv[q]);
                        H.b[q] = h;
                        L.b[q] = __float2half(vv[q] - __half2float(h));
                    }
                    __half* rowp = Ab2 + grow * KSPLIT + gcol + f * 4;
                    *(uint2*)(rowp)      = H.u;
                    *(uint2*)(rowp + EE) = L.u;
                }
            }
        }
        __syncwarp();
    }
}

// ---------------------------------------------------------------------------
// qin = X @ Wi + bi    (16384x8, K=1024) : one warp per row
// ---------------------------------------------------------------------------
__global__ __launch_bounds__(256) void qin_kernel(const float* __restrict__ X,
                                                  const float* __restrict__ Wi,
                                                  const float* __restrict__ bi) {
    __shared__ float sWi[NQ * EE];
    int tid = threadIdx.x;
    for (int idx = tid; idx < EE * NQ; idx += 256) {
        int k = idx >> 3, o = idx & 7;
        sWi[o * EE + k] = Wi[idx];
    }
    __syncthreads();

    int w = tid >> 5, lane = tid & 31;
    long row = (long)blockIdx.x * 8 + w;
    const float* xr = X + row * EE;

    float acc[NQ];
    #pragma unroll
    for (int o = 0; o < NQ; o++) acc[o] = 0.f;
    for (int k = lane; k < EE; k += 32) {
        float x = xr[k];
        #pragma unroll
        for (int o = 0; o < NQ; o++) acc[o] += x * sWi[o * EE + k];
    }
    float out = 0.f;
    #pragma unroll
    for (int o = 0; o < NQ; o++) {
        float v = acc[o];
        #pragma unroll
        for (int d = 16; d > 0; d >>= 1) v += __shfl_xor_sync(FULLM, v, d);
        if (lane == o) out = v + bi[o];
    }
    if (lane < NQ) d_qin[row * NQ + lane] = out;
}

// ---------------------------------------------------------------------------
// Quantum state sim: one warp per row, state (256 complex) in shared
// [R12 measured-good version]
// ---------------------------------------------------------------------------
__global__ __launch_bounds__(256) void psi_kernel() {
    __shared__ float2 st[8][DIMQ];
    __shared__ float2 gm[NL * NQ * 4];
    __shared__ int    pm[DIMQ];

    int tid = threadIdx.x;
    if (tid < NL * NQ * 4) gm[tid] = d_gates[tid];
    pm[tid] = d_perm[tid];
    __syncthreads();

    int w = tid >> 5, lane = tid & 31;
    long row = (long)blockIdx.x * 8 + w;

    float x = (lane < NQ) ? d_qin[row * NQ + lane] : 0.f;
    float ss, cc;
    sincosf(0.5f * x, &ss, &cc);
    float cq[NQ], sq[NQ];
    #pragma unroll
    for (int q = 0; q < NQ; q++) {
        cq[q] = __shfl_sync(FULLM, cc, q);
        sq[q] = __shfl_sync(FULLM, ss, q);
    }
    #pragma unroll
    for (int j = 0; j < 8; j++) {
        int i = lane + 32 * j;
        float a = 1.f;
        #pragma unroll
        for (int q = 0; q < NQ; q++)
            a *= ((i >> (NQ - 1 - q)) & 1) ? sq[q] : cq[q];
        st[w][i] = make_float2(a, 0.f);
    }
    __syncwarp();

    for (int l = 0; l < NL; l++) {
        #pragma unroll
        for (int q = 0; q < NQ; q++) {
            const float2 m00 = gm[(l * NQ + q) * 4 + 0];
            const float2 m01 = gm[(l * NQ + q) * 4 + 1];
            const float2 m10 = gm[(l * NQ + q) * 4 + 2];
            const float2 m11 = gm[(l * NQ + q) * 4 + 3];
            int stride = 1 << (NQ - 1 - q);
            #pragma unroll
            for (int pp = 0; pp < 4; pp++) {
                int p  = lane + 32 * pp;
                int i0 = ((p & ~(stride - 1)) << 1) | (p & (stride - 1));
                int i1 = i0 | stride;
                float2 a0 = st[w][i0];
                float2 a1 = st[w][i1];
                float2 n0, n1;
                n0.x = m00.x * a0.x - m00.y * a0.y + m01.x * a1.x - m01.y * a1.y;
                n0.y = m00.x * a0.y + m00.y * a0.x + m01.x * a1.y + m01.y * a1.x;
                n1.x = m10.x * a0.x - m10.y * a0.y + m11.x * a1.x - m11.y * a1.y;
                n1.y = m10.x * a0.y + m10.y * a0.x + m11.x * a1.y + m11.y * a1.x;
                st[w][i0] = n0;
                st[w][i1] = n1;
            }
            __syncwarp();
        }
        float2 tmp[8];
        #pragma unroll
        for (int j = 0; j < 8; j++) tmp[j] = st[w][pm[lane + 32 * j]];
        __syncwarp();
        #pragma unroll
        for (int j = 0; j < 8; j++) st[w][lane + 32 * j] = tmp[j];
        __syncwarp();
    }
    #pragma unroll
    for (int j = 0; j < 8; j++)
        d_psi[row * DIMQ + lane + 32 * j] = st[w][lane + 32 * j];
}

// ---------------------------------------------------------------------------
// Gram + kernel-matrix + softmax -> attn (fp32) + fused fp16 [hi|lo] split.
// TWO blocks per batch (64 s-rows each), 512 threads.
// ---------------------------------------------------------------------------
__global__ __launch_bounds__(512) void gram_kernel(const float* __restrict__ phi,
                                                   float* __restrict__ attn,
                                                   __half* __restrict__ attns) {
    const int DC = 16;
    __shared__ float2 P[SS][DC + 1];

    int b   = blockIdx.x;
    int sh  = blockIdx.y;      // 0/1 -> s-rows [sh*64, sh*64+64)
    int tid = threadIdx.x;
    int ts  = tid >> 5;
    int tt  = tid & 31;

    float accr[4][4], acci[4][4];
    #pragma unroll
    for (int j = 0; j < 4; j++)
        #pragma unroll
        for (int k = 0; k < 4; k++) { accr[j][k] = 0.f; acci[j][k] = 0.f; }

    const float2* pb = d_psi + (long)b * SS * DIMQ;

    for (int d0 = 0; d0 < DIMQ; d0 += DC) {
        #pragma unroll
        for (int u = 0; u < 4; u++) {
            int idx = tid + 512 * u;
            int r = idx >> 4, dd = idx & 15;
            P[r][dd] = pb[(long)r * DIMQ + d0 + dd];
        }
        __syncthreads();
        #pragma unroll 4
        for (int dd = 0; dd < DC; dd++) {
            float2 sf[4], tf[4];
            #pragma unroll
            for (int j = 0; j < 4; j++) sf[j] = P[sh * 64 + ts * 4 + j][dd];
            #pragma unroll
            for (int k = 0; k < 4; k++) tf[k] = P[tt + 32 * k][dd];
            #pragma unroll
            for (int j = 0; j < 4; j++)
                #pragma unroll
                for (int k = 0; k < 4; k++) {
                    accr[j][k] += sf[j].x * tf[k].x + sf[j].y * tf[k].y;
                    acci[j][k] += sf[j].y * tf[k].x - sf[j].x * tf[k].y;
                }
        }
        __syncthreads();
    }

    const float inv = 0.3535533905932738f;
    float pht[4];
    #pragma unroll
    for (int k = 0; k < 4; k++) pht[k] = phi[tt + 32 * k];

    #pragma unroll
    for (int j = 0; j < 4; j++) {
        int srow = sh * 64 + ts * 4 + j;
        float ph_s = phi[srow];
        float kv[4];
        float mx = -1e30f;
        #pragma unroll
        for (int k = 0; k < 4; k++) {
            float g2 = accr[j][k] * accr[j][k] + acci[j][k] * acci[j][k];
            kv[k] = g2 * inv + cosf(pht[k] - ph_s);
            mx = fmaxf(mx, kv[k]);
        }
        #pragma unroll
        for (int d = 16; d > 0; d >>= 1) mx = fmaxf(mx, __shfl_xor_sync(FULLM, mx, d));
        float sum = 0.f;
        #pragma unroll
        for (int k = 0; k < 4; k++) { kv[k] = expf(kv[k] - mx); sum += kv[k]; }
        #pragma unroll
        for (int d = 16; d > 0; d >>= 1) sum += __shfl_xor_sync(FULLM, sum, d);
        float is = 1.f / sum;
        long arow = (long)b * SS + srow;
        #pragma unroll
        for (int k = 0; k < 4; k++) {
            float a = kv[k] * is;
            attn[(long)b * SS * SS + (long)srow * SS + tt + 32 * k] = a;
            __half h = __float2half(a);
            __half l = __float2half(a - __half2float(h));
            attns[arow * KAV + tt + 32 * k]      = h;
            attns[arow * KAV + SS + tt + 32 * k] = l;
        }
    }
}

// ---------------------------------------------------------------------------
extern "C" void kernel_launch(void* const* d_in, const int* in_sizes, int n_in,
                              void* d_out, int out_size) {
    const float* X     = (const float*)d_in[0];
    const float* Wi    = (const float*)d_in[1];
    const float* bi    = (const float*)d_in[2];
    const float* Wv    = (const float*)d_in[3];
    const float* bv    = (const float*)d_in[4];
    const float* Wo    = (const float*)d_in[5];
    const float* bo    = (const float*)d_in[6];
    const float* theta = (const float*)d_in[7];
    const float* phi   = (const float*)d_in[8];

    float* y    = (float*)d_out;
    float* attn = (float*)d_out + Y_SIZE;

    __half *pXs, *pTs, *pWvs, *pWos, *pAs, *pVts;
    cudaGetSymbolAddress((void**)&pXs, d_Xs);
    cudaGetSymbolAddress((void**)&pTs, d_Ts);
    cudaGetSymbolAddress((void**)&pWvs, d_Wvs);
    cudaGetSymbolAddress((void**)&pWos, d_Wos);
    cudaGetSymbolAddress((void**)&pAs, d_attns);
    cudaGetSymbolAddress((void**)&pVts, d_Vts);

    // dynamic smem opt-in (host-side attribute config; idempotent)
    cudaFuncSetAttribute((const void*)wgemm_kernel<KSPLIT, KSPLIT / 32, 0>,
                         cudaFuncAttributeMaxDynamicSharedMemorySize, WG_SMEM);
    cudaFuncSetAttribute((const void*)wgemm_kernel<KSPLIT, KSPLIT / 32, 2>,
                         cudaFuncAttributeMaxDynamicSharedMemorySize, WG_SMEM);
    cudaFuncSetAttribute((const void*)wgemm_kernel<KAV, KAV / 32, 1>,
                         cudaFuncAttributeMaxDynamicSharedMemorySize, WG_SMEM);

    // prep + splits
    prep_kernel<<<1, 256>>>(theta);
    {
        dim3 g(EE / 32, EE / 32);
        splitB_kernel<<<g, 256>>>(Wv, pWvs);
        splitB_kernel<<<g, 256>>>(Wo, pWos);
    }
    splitA_kernel<<<ROWS, 256>>>(X, pXs);
    qin_kernel<<<ROWS / 8, 256>>>(X, Wi, bi);

    // V GEMM: X@Wv + bv -> DIRECTLY into Vts [b][e][hi|hi] (MODE 2, no fp32 V)
    {
        dim3 grid(EE / 128, ROWS / 128, 1);
        wgemm_kernel<KSPLIT, KSPLIT / 32, 2><<<grid, 256, WG_SMEM>>>(
            pXs, pWvs, bv, nullptr, pVts, 0, 0, 0);
    }

    // quantum states + Gram/softmax (writes fp32 attn + fp16 split)
    psi_kernel<<<ROWS / 8, 256>>>();
    gram_kernel<<<dim3(NB, 2), 512>>>(phi, attn, pAs);

    // T = attn @ V (wmma, batched over z) -> emits Ts = [hi|lo] fp16 directly
    {
        dim3 grid(EE / 128, 1, NB);
        wgemm_kernel<KAV, KAV / 32, 1><<<grid, 256, WG_SMEM>>>(
            pAs, pVts, nullptr, nullptr, pTs,
            (long)SS * KAV, (long)EE * KAV, (long)SS * KSPLIT);
    }

    // y = T @ Wo + bo (wmma fp16 2-term, 3-stage pipeline)
    {
        dim3 grid(EE / 128, ROWS / 128, 1);
        wgemm_kernel<KSPLIT, KSPLIT / 32, 0><<<grid, 256, WG_SMEM>>>(
            pTs, pWos, bo, y, nullptr, 0, 0, 0);
    }
}

// round 17
// speedup vs baseline: 1.7728x; 1.1365x over previous
#include <cuda_runtime.h>
#include <cuda_fp16.h>
#include <mma.h>
#include <math.h>
#include <stdint.h>

using namespace nvcuda;

// Problem constants (fixed shapes)
#define NB      128          // batch
#define SS      128          // seq
#define EE      1024         // embed
#define NQ      8            // qubits
#define NL      4            // layers
#define DIMQ    256          // 2^NQ
#define ROWS    16384        // NB*SS
#define KSPLIT  2048         // 2*EE  (fp16 2-term split: A=[hi|lo], B=[hi|hi])
#define KAV     256          // 2*SS  (attn@V split K)
#define Y_SIZE  16777216L    // NB*SS*EE

// Scratch (static device globals — allowed)
__device__ float  d_qin[ROWS * NQ];
__device__ float2 d_gates[NL * NQ * 4];
__device__ int    d_perm[DIMQ];
__device__ float2 d_psi[(long)ROWS * DIMQ];
__device__ __half d_Xs[(long)ROWS * KSPLIT];    // split X    [M][2K]
__device__ __half d_Ts[(long)ROWS * KSPLIT];    // split T    [M][2K]  (written by attn@V wgemm)
__device__ __half d_Wvs[(long)EE * KSPLIT];     // Wv^T       [N][2K] = [hi|hi]
__device__ __half d_Wos[(long)EE * KSPLIT];     // Wo^T       [N][2K] = [hi|hi]
__device__ __half d_attns[(long)ROWS * KAV];    // split attn [b*s][2*128] (written by gram)
__device__ __half d_Vts[(long)NB * EE * KAV];   // V^T        [b][e][2*128] = [hi|hi] (written by V wgemm)

#define FULLM 0xffffffffu

// ---------------------------------------------------------------------------
// cp.async helpers (sm_80+ baseline — no 'a'-suffix features!)
// ---------------------------------------------------------------------------
__device__ __forceinline__ uint32_t smem_u32(const void* p) {
    uint32_t a;
    asm("{ .reg .u64 t; cvta.to.shared.u64 t, %1; cvt.u32.u64 %0, t; }" : "=r"(a) : "l"(p));
    return a;
}
__device__ __forceinline__ void cp16(uint32_t s, const void* g) {
    asm volatile("cp.async.cg.shared.global [%0], [%1], 16;" :: "r"(s), "l"(g));
}
#define CP_COMMIT() asm volatile("cp.async.commit_group;" ::: "memory")
#define CP_WAIT2()  asm volatile("cp.async.wait_group 2;" ::: "memory")
#define CP_WAIT1()  asm volatile("cp.async.wait_group 1;" ::: "memory")
#define CP_WAIT0()  asm volatile("cp.async.wait_group 0;" ::: "memory")

// ---------------------------------------------------------------------------
// Prep: fused RZ*RY gate matrices, composed CNOT-ring perm
// ---------------------------------------------------------------------------
__global__ void prep_kernel(const float* __restrict__ theta) {
    int t = threadIdx.x;
    if (t < NL * NQ) {
        float ty = theta[t * 2 + 0];
        float tz = theta[t * 2 + 1];
        float s, c, zs, zc;
        sincosf(0.5f * ty, &s, &c);
        sincosf(0.5f * tz, &zs, &zc);
        d_gates[t * 4 + 0] = make_float2( c * zc, -c * zs);
        d_gates[t * 4 + 1] = make_float2(-s * zc,  s * zs);
        d_gates[t * 4 + 2] = make_float2( s * zc,  s * zs);
        d_gates[t * 4 + 3] = make_float2( c * zc,  c * zs);
    }
    if (t < DIMQ) {
        int j = t;
        #pragma unroll
        for (int q = NQ - 1; q >= 0; q--) {
            int tq   = (q + 1) & (NQ - 1);
            int cpos = NQ - 1 - q;
            int tpos = NQ - 1 - tq;
            if ((j >> cpos) & 1) j ^= (1 << tpos);
        }
        d_perm[t] = j;
    }
}

// ---------------------------------------------------------------------------
// splitA: fp32 [R x 1024] -> fp16 [R x 2048] laid out [hi | lo]
// ---------------------------------------------------------------------------
__global__ __launch_bounds__(256) void splitA_kernel(const float* __restrict__ src,
                                                     __half* __restrict__ dst) {
    long i = (long)blockIdx.x * 256 + threadIdx.x;   // float4 index
    float4 v = ((const float4*)src)[i];
    long r  = i >> 8;
    int  c4 = (int)(i & 255) * 4;
    float vv[4] = {v.x, v.y, v.z, v.w};
    union { __half b[4]; uint2 u; } H, L;
    #pragma unroll
    for (int j = 0; j < 4; j++) {
        __half h = __float2half(vv[j]);
        H.b[j] = h;
        L.b[j] = __float2half(vv[j] - __half2float(h));
    }
    __half* row = dst + r * KSPLIT;
    *(uint2*)(row + c4)      = H.u;
    *(uint2*)(row + EE + c4) = L.u;
}

// ---------------------------------------------------------------------------
// splitB: W fp32 [K=1024][N=1024] -> Bt fp16 [N][2048] = [hi | hi] transposed
// ---------------------------------------------------------------------------
__global__ __launch_bounds__(256) void splitB_kernel(const float* __restrict__ W,
                                                     __half* __restrict__ Bt) {
    __shared__ float tile[32][33];
    int k0 = blockIdx.y * 32, n0 = blockIdx.x * 32;
    int tx = threadIdx.x & 31, ty = threadIdx.x >> 5;  // 32 x 8
    #pragma unroll
    for (int j = 0; j < 32; j += 8)
        tile[ty + j][tx] = W[(long)(k0 + ty + j) * EE + n0 + tx];
    __syncthreads();
    #pragma unroll
    for (int j = 0; j < 32; j += 8) {
        int n = n0 + ty + j, k = k0 + tx;
        __half h = __float2half(tile[tx][ty + j]);
        __half* row = Bt + (long)n * KSPLIT;
        row[k]      = h;
        row[EE + k] = h;
    }
}

// ---------------------------------------------------------------------------
// wmma (HMMA) fp16 GEMM: C = A'[M,LDA] x B'[1024,LDA]^T, z-batched.
// BM=BN=128, BK=64, 256 threads (8 warps, 4x2), warp tile 32x64 (2x4 frags),
// THREE-stage cp.async pipeline.  Stage = [A 18432B | B 18432B] = 36864B.
// MODE 0: fp32 C (stride EE) + bias.
// MODE 1: fp16 [hi|lo] out (row stride KSPLIT).
// MODE 2: fp16 [hi|hi] TRANSPOSED out into Vts[b][e][KAV] + bias (V GEMM).
// ---------------------------------------------------------------------------
#define WG_BK     64
#define WG_LDS    72                  // smem row stride (fp16 elems), 144 bytes
#define WG_HALF   (128 * WG_LDS)      // 9216 elems = 18432 bytes per matrix
#define WG_STAGE  (2 * WG_HALF * 2)   // A+B per stage = 36864 bytes
#define WG_NSTG   3
#define WG_SMEM   (WG_NSTG * WG_STAGE)  // 110592 bytes

template<int LDA, int NCH, int MODE>
__global__ __launch_bounds__(256) void wgemm_kernel(
    const __half* __restrict__ A, const __half* __restrict__ B,
    const float* __restrict__ bias, float* __restrict__ C,
    __half* __restrict__ aux, long sA, long sB, long sC) {
    extern __shared__ __align__(16) char smem_raw[];
    uint32_t sbase = smem_u32(smem_raw);

    int tid  = threadIdx.x;
    int wid  = tid >> 5, lane = tid & 31;
    int wm   = wid & 3;         // warp row: rows [wm*32, wm*32+32)
    int wn   = wid >> 2;        // warp col: cols [wn*64, wn*64+64)

    long bz = blockIdx.z;
    const __half* Ab = A + bz * sA;
    const __half* Bb = B + bz * sB;

    long m0 = (long)blockIdx.y * 128;
    int  n0 = blockIdx.x * 128;

    // cp.async mapping: tile 128x64 fp16 = 1024 x 16B segs; 4 per thread per matrix.
    uint32_t dstO[4];
    const char* srcA[4];
    const char* srcB[4];
    #pragma unroll
    for (int u = 0; u < 4; u++) {
        int idx = tid + 256 * u;
        int row = idx >> 3, seg = idx & 7;       // 8 segs (128B) per row
        dstO[u] = (uint32_t)row * (WG_LDS * 2) + seg * 16;
        srcA[u] = (const char*)(Ab + (m0 + row) * (long)LDA) + seg * 16;
        srcB[u] = (const char*)(Bb + (long)(n0 + row) * LDA) + seg * 16;
    }

    wmma::fragment<wmma::accumulator, 16, 16, 16, float> acc[2][4];
    #pragma unroll
    for (int i = 0; i < 2; i++)
        #pragma unroll
        for (int j = 0; j < 4; j++) wmma::fill_fragment(acc[i][j], 0.f);

    // prologue: chunks 0,1 -> stages 0,1   (B at byte offset 2*WG_HALF)
    #pragma unroll
    for (int p = 0; p < 2; p++) {
        uint32_t st = sbase + p * WG_STAGE;
        long gofs = (long)p * (WG_BK * 2);   // 64 fp16 = 128 bytes per chunk
        #pragma unroll
        for (int u = 0; u < 4; u++) {
            cp16(st + dstO[u], srcA[u] + gofs);
            cp16(st + 2 * WG_HALF + dstO[u], srcB[u] + gofs);
        }
        CP_COMMIT();
    }

    int stage = 0;      // stage holding chunk ch
    int nstage = 2;     // stage to fill with chunk ch+2
    #pragma unroll 1
    for (int ch = 0; ch < NCH; ch++) {
        if (ch + 2 < NCH) {
            uint32_t st = sbase + nstage * WG_STAGE;
            long gofs = (long)(ch + 2) * (WG_BK * 2);
            #pragma unroll
            for (int u = 0; u < 4; u++) {
                cp16(st + dstO[u], srcA[u] + gofs);
                cp16(st + 2 * WG_HALF + dstO[u], srcB[u] + gofs);
            }
            CP_COMMIT();
            CP_WAIT2();
        } else if (ch + 1 < NCH) {
            CP_WAIT1();
        } else {
            CP_WAIT0();
        }
        __syncthreads();

        const __half* bufA = (const __half*)(smem_raw + stage * WG_STAGE);
        const __half* bufB = bufA + WG_HALF;   // +9216 elems = +18432 BYTES (matches store)

        #pragma unroll
        for (int kk = 0; kk < WG_BK; kk += 16) {
            wmma::fragment<wmma::matrix_a, 16, 16, 16, __half, wmma::row_major> af[2];
            wmma::fragment<wmma::matrix_b, 16, 16, 16, __half, wmma::col_major> bf[4];
            #pragma unroll
            for (int i = 0; i < 2; i++)
                wmma::load_matrix_sync(af[i], bufA + (wm * 32 + i * 16) * WG_LDS + kk, WG_LDS);
            #pragma unroll
            for (int j = 0; j < 4; j++)
                wmma::load_matrix_sync(bf[j], bufB + (wn * 64 + j * 16) * WG_LDS + kk, WG_LDS);
            #pragma unroll
            for (int i = 0; i < 2; i++)
                #pragma unroll
                for (int j = 0; j < 4; j++)
                    wmma::mma_sync(acc[i][j], af[i], bf[j], acc[i][j]);
        }
        __syncthreads();
        stage  = (stage == WG_NSTG - 1) ? 0 : stage + 1;
        nstage = (nstage == WG_NSTG - 1) ? 0 : nstage + 1;
    }

    // Epilogue: per-warp SMEM staging (16x68 f32) -> stores by MODE
    float* stag = (float*)smem_raw + wid * (16 * 68);   // 8 warps x 4352B = 34816
    int erow = lane >> 1, ecb = (lane & 1) * 32;
    float* Cb = (MODE == 0) ? (C + bz * sC) : nullptr;
    __half* Ab2 = (MODE == 1) ? (aux + bz * sC) : nullptr;
    #pragma unroll
    for (int mi = 0; mi < 2; mi++) {
        #pragma unroll
        for (int j = 0; j < 4; j++)
            wmma::store_matrix_sync(stag + j * 16, acc[mi][j], 68, wmma::mem_row_major);
        __syncwarp();
        if (MODE == 2) {
            // Transposed fp16 [hi|hi] output with bias: Vts[(b*EE + e)*KAV + t].
            int b  = blockIdx.y;
            int tb = wm * 32 + mi * 16;
            #pragma unroll
            for (int cc = 0; cc < 2; cc++) {
                int ecol = lane * 2 + cc;             // 0..63
                int eg   = n0 + wn * 64 + ecol;
                float be = bias[eg];
                union { __half h[16]; uint4 u[2]; } pk;
                #pragma unroll
                for (int r = 0; r < 16; r++)
                    pk.h[r] = __float2half(stag[r * 68 + ecol] + be);
                __half* rowp = aux + ((long)b * EE + eg) * KAV + tb;
                *(uint4*)(rowp)          = pk.u[0];
                *(uint4*)(rowp + 8)      = pk.u[1];
                *(uint4*)(rowp + SS)     = pk.u[0];
                *(uint4*)(rowp + SS + 8) = pk.u[1];
            }
        } else {
            long grow = m0 + wm * 32 + mi * 16 + erow;
            int  gcol = n0 + wn * 64 + ecb;
            #pragma unroll
            for (int f = 0; f < 8; f++) {
                float4 v = *(float4*)(stag + erow * 68 + ecb + f * 4);
                if (MODE == 0) {
                    if (bias) {
                        float4 b4 = *(const float4*)(bias + gcol + f * 4);
                        v.x += b4.x; v.y += b4.y; v.z += b4.z; v.w += b4.w;
                    }
                    *(float4*)(Cb + grow * EE + gcol + f * 4) = v;
                } else {
                    float vv[4] = {v.x, v.y, v.z, v.w};
                    union { __half b[4]; uint2 u; } H, L;
                    #pragma unroll
                    for (int q = 0; q < 4; q++) {
                        __half h = __float2half(vv[q]);
                        H.b[q] = h;
                        L.b[q] = __float2half(vv[q] - __half2float(h));
                    }
                    __half* rowp = Ab2 + grow * KSPLIT + gcol + f * 4;
                    *(uint2*)(rowp)      = H.u;
                    *(uint2*)(rowp + EE) = L.u;
                }
            }
        }
        __syncwarp();
    }
}

// ---------------------------------------------------------------------------
// qin = X @ Wi + bi    (16384x8, K=1024) : one warp per row
// ---------------------------------------------------------------------------
__global__ __launch_bounds__(256) void qin_kernel(const float* __restrict__ X,
                                                  const float* __restrict__ Wi,
                                                  const float* __restrict__ bi) {
    __shared__ float sWi[NQ * EE];
    int tid = threadIdx.x;
    for (int idx = tid; idx < EE * NQ; idx += 256) {
        int k = idx >> 3, o = idx & 7;
        sWi[o * EE + k] = Wi[idx];
    }
    __syncthreads();

    int w = tid >> 5, lane = tid & 31;
    long row = (long)blockIdx.x * 8 + w;
    const float* xr = X + row * EE;

    float acc[NQ];
    #pragma unroll
    for (int o = 0; o < NQ; o++) acc[o] = 0.f;
    for (int k = lane; k < EE; k += 32) {
        float x = xr[k];
        #pragma unroll
        for (int o = 0; o < NQ; o++) acc[o] += x * sWi[o * EE + k];
    }
    float out = 0.f;
    #pragma unroll
    for (int o = 0; o < NQ; o++) {
        float v = acc[o];
        #pragma unroll
        for (int d = 16; d > 0; d >>= 1) v += __shfl_xor_sync(FULLM, v, d);
        if (lane == o) out = v + bi[o];
    }
    if (lane < NQ) d_qin[row * NQ + lane] = out;
}

// ---------------------------------------------------------------------------
// Quantum state sim: one warp per row, state (256 complex) in shared
// [R12/R16 measured-good version]
// ---------------------------------------------------------------------------
__global__ __launch_bounds__(256) void psi_kernel() {
    __shared__ float2 st[8][DIMQ];
    __shared__ float2 gm[NL * NQ * 4];
    __shared__ int    pm[DIMQ];

    int tid = threadIdx.x;
    if (tid < NL * NQ * 4) gm[tid] = d_gates[tid];
    pm[tid] = d_perm[tid];
    __syncthreads();

    int w = tid >> 5, lane = tid & 31;
    long row = (long)blockIdx.x * 8 + w;

    float x = (lane < NQ) ? d_qin[row * NQ + lane] : 0.f;
    float ss, cc;
    sincosf(0.5f * x, &ss, &cc);
    float cq[NQ], sq[NQ];
    #pragma unroll
    for (int q = 0; q < NQ; q++) {
        cq[q] = __shfl_sync(FULLM, cc, q);
        sq[q] = __shfl_sync(FULLM, ss, q);
    }
    #pragma unroll
    for (int j = 0; j < 8; j++) {
        int i = lane + 32 * j;
        float a = 1.f;
        #pragma unroll
        for (int q = 0; q < NQ; q++)
            a *= ((i >> (NQ - 1 - q)) & 1) ? sq[q] : cq[q];
        st[w][i] = make_float2(a, 0.f);
    }
    __syncwarp();

    for (int l = 0; l < NL; l++) {
        #pragma unroll
        for (int q = 0; q < NQ; q++) {
            const float2 m00 = gm[(l * NQ + q) * 4 + 0];
            const float2 m01 = gm[(l * NQ + q) * 4 + 1];
            const float2 m10 = gm[(l * NQ + q) * 4 + 2];
            const float2 m11 = gm[(l * NQ + q) * 4 + 3];
            int stride = 1 << (NQ - 1 - q);
            #pragma unroll
            for (int pp = 0; pp < 4; pp++) {
                int p  = lane + 32 * pp;
                int i0 = ((p & ~(stride - 1)) << 1) | (p & (stride - 1));
                int i1 = i0 | stride;
                float2 a0 = st[w][i0];
                float2 a1 = st[w][i1];
                float2 n0, n1;
                n0.x = m00.x * a0.x - m00.y * a0.y + m01.x * a1.x - m01.y * a1.y;
                n0.y = m00.x * a0.y + m00.y * a0.x + m01.x * a1.y + m01.y * a1.x;
                n1.x = m10.x * a0.x - m10.y * a0.y + m11.x * a1.x - m11.y * a1.y;
                n1.y = m10.x * a0.y + m10.y * a0.x + m11.x * a1.y + m11.y * a1.x;
                st[w][i0] = n0;
                st[w][i1] = n1;
            }
            __syncwarp();
        }
        float2 tmp[8];
        #pragma unroll
        for (int j = 0; j < 8; j++) tmp[j] = st[w][pm[lane + 32 * j]];
        __syncwarp();
        #pragma unroll
        for (int j = 0; j < 8; j++) st[w][lane + 32 * j] = tmp[j];
        __syncwarp();
    }
    #pragma unroll
    for (int j = 0; j < 8; j++)
        d_psi[row * DIMQ + lane + 32 * j] = st[w][lane + 32 * j];
}

// ---------------------------------------------------------------------------
// Gram + kernel-matrix + softmax -> attn (fp32) + fused fp16 [hi|lo] split.
// TWO blocks per batch (64 s-rows each), 512 threads. DC=32 (16 sync pairs -> 8).
// ---------------------------------------------------------------------------
__global__ __launch_bounds__(512) void gram_kernel(const float* __restrict__ phi,
                                                   float* __restrict__ attn,
                                                   __half* __restrict__ attns) {
    const int DC = 32;
    __shared__ float2 P[SS][DC + 1];   // 128 x 33 float2 = 33792 B

    int b   = blockIdx.x;
    int sh  = blockIdx.y;      // 0/1 -> s-rows [sh*64, sh*64+64)
    int tid = threadIdx.x;
    int ts  = tid >> 5;
    int tt  = tid & 31;

    float accr[4][4], acci[4][4];
    #pragma unroll
    for (int j = 0; j < 4; j++)
        #pragma unroll
        for (int k = 0; k < 4; k++) { accr[j][k] = 0.f; acci[j][k] = 0.f; }

    const float2* pb = d_psi + (long)b * SS * DIMQ;

    for (int d0 = 0; d0 < DIMQ; d0 += DC) {
        #pragma unroll
        for (int u = 0; u < 8; u++) {
            int idx = tid + 512 * u;          // 0..4095
            int r = idx >> 5, dd = idx & 31;
            P[r][dd] = pb[(long)r * DIMQ + d0 + dd];
        }
        __syncthreads();
        #pragma unroll 4
        for (int dd = 0; dd < DC; dd++) {
            float2 sf[4], tf[4];
            #pragma unroll
            for (int j = 0; j < 4; j++) sf[j] = P[sh * 64 + ts * 4 + j][dd];
            #pragma unroll
            for (int k = 0; k < 4; k++) tf[k] = P[tt + 32 * k][dd];
            #pragma unroll
            for (int j = 0; j < 4; j++)
                #pragma unroll
                for (int k = 0; k < 4; k++) {
                    accr[j][k] += sf[j].x * tf[k].x + sf[j].y * tf[k].y;
                    acci[j][k] += sf[j].y * tf[k].x - sf[j].x * tf[k].y;
                }
        }
        __syncthreads();
    }

    const float inv = 0.3535533905932738f;
    float pht[4];
    #pragma unroll
    for (int k = 0; k < 4; k++) pht[k] = phi[tt + 32 * k];

    #pragma unroll
    for (int j = 0; j < 4; j++) {
        int srow = sh * 64 + ts * 4 + j;
        float ph_s = phi[srow];
        float kv[4];
        float mx = -1e30f;
        #pragma unroll
        for (int k = 0; k < 4; k++) {
            float g2 = accr[j][k] * accr[j][k] + acci[j][k] * acci[j][k];
            kv[k] = g2 * inv + cosf(pht[k] - ph_s);
            mx = fmaxf(mx, kv[k]);
        }
        #pragma unroll
        for (int d = 16; d > 0; d >>= 1) mx = fmaxf(mx, __shfl_xor_sync(FULLM, mx, d));
        float sum = 0.f;
        #pragma unroll
        for (int k = 0; k < 4; k++) { kv[k] = expf(kv[k] - mx); sum += kv[k]; }
        #pragma unroll
        for (int d = 16; d > 0; d >>= 1) sum += __shfl_xor_sync(FULLM, sum, d);
        float is = 1.f / sum;
        long arow = (long)b * SS + srow;
        #pragma unroll
        for (int k = 0; k < 4; k++) {
            float a = kv[k] * is;
            attn[(long)b * SS * SS + (long)srow * SS + tt + 32 * k] = a;
            __half h = __float2half(a);
            __half l = __float2half(a - __half2float(h));
            attns[arow * KAV + tt + 32 * k]      = h;
            attns[arow * KAV + SS + tt + 32 * k] = l;
        }
    }
}

// ---------------------------------------------------------------------------
extern "C" void kernel_launch(void* const* d_in, const int* in_sizes, int n_in,
                              void* d_out, int out_size) {
    const float* X     = (const float*)d_in[0];
    const float* Wi    = (const float*)d_in[1];
    const float* bi    = (const float*)d_in[2];
    const float* Wv    = (const float*)d_in[3];
    const float* bv    = (const float*)d_in[4];
    const float* Wo    = (const float*)d_in[5];
    const float* bo    = (const float*)d_in[6];
    const float* theta = (const float*)d_in[7];
    const float* phi   = (const float*)d_in[8];

    float* y    = (float*)d_out;
    float* attn = (float*)d_out + Y_SIZE;

    __half *pXs, *pTs, *pWvs, *pWos, *pAs, *pVts;
    cudaGetSymbolAddress((void**)&pXs, d_Xs);
    cudaGetSymbolAddress((void**)&pTs, d_Ts);
    cudaGetSymbolAddress((void**)&pWvs, d_Wvs);
    cudaGetSymbolAddress((void**)&pWos, d_Wos);
    cudaGetSymbolAddress((void**)&pAs, d_attns);
    cudaGetSymbolAddress((void**)&pVts, d_Vts);

    // dynamic smem opt-in (host-side attribute config; idempotent)
    cudaFuncSetAttribute((const void*)wgemm_kernel<KSPLIT, KSPLIT / WG_BK, 0>,
                         cudaFuncAttributeMaxDynamicSharedMemorySize, WG_SMEM);
    cudaFuncSetAttribute((const void*)wgemm_kernel<KSPLIT, KSPLIT / WG_BK, 2>,
                         cudaFuncAttributeMaxDynamicSharedMemorySize, WG_SMEM);
    cudaFuncSetAttribute((const void*)wgemm_kernel<KAV, KAV / WG_BK, 1>,
                         cudaFuncAttributeMaxDynamicSharedMemorySize, WG_SMEM);

    // prep + splits
    prep_kernel<<<1, 256>>>(theta);
    {
        dim3 g(EE / 32, EE / 32);
        splitB_kernel<<<g, 256>>>(Wv, pWvs);
        splitB_kernel<<<g, 256>>>(Wo, pWos);
    }
    splitA_kernel<<<ROWS, 256>>>(X, pXs);
    qin_kernel<<<ROWS / 8, 256>>>(X, Wi, bi);

    // V GEMM: X@Wv + bv -> DIRECTLY into Vts [b][e][hi|hi] (MODE 2, no fp32 V)
    {
        dim3 grid(EE / 128, ROWS / 128, 1);
        wgemm_kernel<KSPLIT, KSPLIT / WG_BK, 2><<<grid, 256, WG_SMEM>>>(
            pXs, pWvs, bv, nullptr, pVts, 0, 0, 0);
    }

    // quantum states + Gram/softmax (writes fp32 attn + fp16 split)
    psi_kernel<<<ROWS / 8, 256>>>();
    gram_kernel<<<dim3(NB, 2), 512>>>(phi, attn, pAs);

    // T = attn @ V (wmma, batched over z) -> emits Ts = [hi|lo] fp16 directly
    {
        dim3 grid(EE / 128, 1, NB);
        wgemm_kernel<KAV, KAV / WG_BK, 1><<<grid, 256, WG_SMEM>>>(
            pAs, pVts, nullptr, nullptr, pTs,
            (long)SS * KAV, (long)EE * KAV, (long)SS * KSPLIT);
    }

    // y = T @ Wo + bo (wmma fp16 2-term, 3-stage pipeline)
    {
        dim3 grid(EE / 128, ROWS / 128, 1);
        wgemm_kernel<KSPLIT, KSPLIT / WG_BK, 0><<<grid, 256, WG_SMEM>>>(
            pTs, pWos, bo, y, nullptr, 0, 0, 0);
    }
}